// round 15
// baseline (speedup 1.0000x reference)
#include <cuda_runtime.h>
#include <cstdint>

// ---------------------------------------------------------------------------
// Common math (byte-identical to R5..R14 proven chain)
// ---------------------------------------------------------------------------
__device__ __forceinline__ float rcp_approx_(float x) {
    float r;
    asm("rcp.approx.f32 %0, %1;" : "=f"(r) : "f"(x));
    return r;
}

#define GMF_D 0.16666667163372039794921875  /* fp32(1/6) = 0x3E2AAAAB, as double */

// Core: one float8 (half of a 16-elem group). Lane PAIRS own whole groups.
__device__ __forceinline__ void quant_f8_(const float x[8], float y[8]) {
    const float C   = (float)(1.0 / (6.0 * GMF_D));   // RN(1/(6*gm))
    const float GMH = (float)(GMF_D * 0.5);           // gm/2, exact halving

    float a01 = fmaxf(fabsf(x[0]), fabsf(x[1]));
    float a23 = fmaxf(fabsf(x[2]), fabsf(x[3]));
    float a45 = fmaxf(fabsf(x[4]), fabsf(x[5]));
    float a67 = fmaxf(fabsf(x[6]), fabsf(x[7]));
    float ax  = fmaxf(fmaxf(a01, a23), fmaxf(a45, a67));
    ax = fmaxf(ax, __shfl_xor_sync(0xFFFFFFFFu, ax, 1));

    float sraw = ax * C;

    unsigned res = (__float_as_uint(sraw) + 0x7FFFFu) & 0xFFF00000u;
    res = max(res, 0x3C000000u);   // 2^-7
    res = min(res, 0x43F00000u);   // 480
    float scale = __uint_as_float(res);

    float R2  = 12.0f * rcp_approx_(scale);
    float sg2 = scale * GMH;

#pragma unroll
    for (int i = 0; i < 8; i++) {
        float u = x[i] * R2;
        float a = fabsf(u);
        float a2 = fminf(fmaxf(a, 2.0f), 12.0f);
        unsigned qb = (__float_as_uint(a2) + 0x00201000u) & 0xFFC00000u;
        float q = __uint_as_float(qb);
        q = (a >= 1.49951171875f)   ? q : 1.0f;
        q = (a >= 0.4998779296875f) ? q : 0.0f;
        float qs = __uint_as_float(__float_as_uint(q) |
                                   (__float_as_uint(u) & 0x80000000u));
        y[i] = qs * sg2;
    }
}

// Output stays L2-resident across graph replays (dirty lines overwritten in
// place -> steady-state DRAM writes ~0). Input is prefetched via async bulk
// copies, so read latency is off the critical path.
__device__ __forceinline__ void stg256_resident_(float* p, const float r[8]) {
    asm volatile("st.global.L2::evict_last.v8.f32 "
                 "[%0], {%1,%2,%3,%4,%5,%6,%7,%8};"
                 :: "l"(p),
                    "f"(r[0]), "f"(r[1]), "f"(r[2]), "f"(r[3]),
                    "f"(r[4]), "f"(r[5]), "f"(r[6]), "f"(r[7])
                 : "memory");
}

// Fallback-path accessors (R14 policy: input resident, output streams).
__device__ __forceinline__ void ldg256_(const float* p, float r[8]) {
    asm volatile("ld.global.nc.L2::evict_last.v8.f32 "
                 "{%0,%1,%2,%3,%4,%5,%6,%7}, [%8];"
                 : "=f"(r[0]), "=f"(r[1]), "=f"(r[2]), "=f"(r[3]),
                   "=f"(r[4]), "=f"(r[5]), "=f"(r[6]), "=f"(r[7])
                 : "l"(p));
}
__device__ __forceinline__ void stg256_stream_(float* p, const float r[8]) {
    asm volatile("st.global.L2::evict_first.v8.f32 "
                 "[%0], {%1,%2,%3,%4,%5,%6,%7,%8};"
                 :: "l"(p),
                    "f"(r[0]), "f"(r[1]), "f"(r[2]), "f"(r[3]),
                    "f"(r[4]), "f"(r[5]), "f"(r[6]), "f"(r[7])
                 : "memory");
}

// ---------------------------------------------------------------------------
// Async-bulk pipelined kernel
// ---------------------------------------------------------------------------
#define THREADS     256
#define TILE_FLOATS 8192                 /* 32 KB per tile, 512 groups */
#define TILE_BYTES  (TILE_FLOATS * 4)
#define STAGES      3                    /* 96 KB dynamic smem -> 2 CTAs/SM */
#define PIPE_GRID   304                  /* 152 SMs x 2 CTAs */

__device__ __forceinline__ uint32_t smem_u32_(const void* p) {
    uint32_t a;
    asm("{ .reg .u64 t; cvta.to.shared.u64 t, %1; cvt.u32.u64 %0, t; }"
        : "=r"(a) : "l"(p));
    return a;
}

__device__ __forceinline__ void mbar_wait_(uint32_t mbar, unsigned parity) {
    unsigned done;
    asm volatile(
        "{ .reg .pred p; mbarrier.try_wait.parity.shared::cta.b64 p, [%1], %2;"
        " selp.b32 %0, 1, 0, p; }"
        : "=r"(done) : "r"(mbar), "r"(parity) : "memory");
    while (!done) {
        asm volatile(
            "{ .reg .pred p; mbarrier.try_wait.parity.shared::cta.b64 p, [%1], %2, 10000000;"
            " selp.b32 %0, 1, 0, p; }"
            : "=r"(done) : "r"(mbar), "r"(parity) : "memory");
    }
}

__device__ __forceinline__ void issue_bulk_(uint32_t dst_smem, const float* src,
                                            uint32_t mbar, uint64_t pol) {
    asm volatile("mbarrier.arrive.expect_tx.shared::cta.b64 _, [%0], %1;"
                 :: "r"(mbar), "r"((unsigned)TILE_BYTES) : "memory");
    asm volatile(
        "cp.async.bulk.shared::cta.global.mbarrier::complete_tx::bytes"
        ".L2::cache_hint [%0], [%1], %2, [%3], %4;"
        :: "r"(dst_smem), "l"(src), "r"((unsigned)TILE_BYTES),
           "r"(mbar), "l"(pol)
        : "memory");
}

__global__ __launch_bounds__(THREADS)
void actquant_nvfp4_pipe(const float* __restrict__ in,
                         float* __restrict__ out,
                         int ntiles) {
    extern __shared__ float smem[];                 // STAGES * TILE_FLOATS
    __shared__ uint64_t mbar_sh[STAGES];

    const int tid = threadIdx.x;

    // Streaming-input L2 policy: never displace the resident output.
    uint64_t pol;
    asm("createpolicy.fractional.L2::evict_first.b64 %0, 1.0;" : "=l"(pol));

    uint32_t mbar_u32[STAGES];
#pragma unroll
    for (int s = 0; s < STAGES; s++) mbar_u32[s] = smem_u32_(&mbar_sh[s]);

    if (tid == 0) {
#pragma unroll
        for (int s = 0; s < STAGES; s++)
            asm volatile("mbarrier.init.shared::cta.b64 [%0], 1;"
                         :: "r"(mbar_u32[s]) : "memory");
        asm volatile("fence.proxy.async.shared::cta;" ::: "memory");
    }
    __syncthreads();

    // Tiles for this CTA: bid, bid+grid, bid+2*grid, ...
    const int bid   = blockIdx.x;
    const int gsz   = gridDim.x;
    const int count = (ntiles - bid + gsz - 1) / gsz;   // bid < ntiles

    // Prologue: fill the pipeline.
    if (tid == 0) {
        int pre = count < STAGES ? count : STAGES;
        for (int s = 0; s < pre; s++) {
            int tile = bid + s * gsz;
            issue_bulk_(smem_u32_(smem + s * TILE_FLOATS),
                        in + (size_t)tile * TILE_FLOATS, mbar_u32[s], pol);
        }
    }

    unsigned ph[STAGES] = {0, 0, 0};

    for (int i = 0; i < count; i++) {
        const int s    = i % STAGES;
        const int tile = bid + i * gsz;

        mbar_wait_(mbar_u32[s], ph[s]);
        ph[s] ^= 1;

        const float* sf = smem + s * TILE_FLOATS;
        float*       op = out + (size_t)tile * TILE_FLOATS;

        // 8192 floats / 256 threads = 4 float8s per thread. Lane pairs own
        // adjacent float8s -> each pair covers one contiguous 16-elem group.
#pragma unroll
        for (int k = 0; k < 4; k++) {
            const int j = tid + k * THREADS;
            const float4* p4 = (const float4*)(sf + (size_t)j * 8);
            float4 lo = p4[0], hi = p4[1];
            float x[8] = {lo.x, lo.y, lo.z, lo.w, hi.x, hi.y, hi.z, hi.w};
            float y[8];
            quant_f8_(x, y);
            stg256_resident_(op + (size_t)j * 8, y);
        }

        __syncthreads();   // all warps done reading stage s

        const int next = i + STAGES;
        if (tid == 0 && next < count) {
            int ntile = bid + next * gsz;
            issue_bulk_(smem_u32_(smem + s * TILE_FLOATS),
                        in + (size_t)ntile * TILE_FLOATS, mbar_u32[s], pol);
        }
    }
}

// ---------------------------------------------------------------------------
// Guarded fallback (== R14 persistent kernel) for non-tile-divisible sizes.
// ---------------------------------------------------------------------------
__global__ __launch_bounds__(256, 7)
void actquant_nvfp4_kernel(const float* __restrict__ in,
                           float* __restrict__ out,
                           int nvec8) {
    const int t = blockIdx.x * blockDim.x + threadIdx.x;
    const int S = gridDim.x * blockDim.x;

    for (int base = t; base < nvec8; base += 2 * S) {
        int idx1 = base + S;
        if (idx1 < nvec8) {
            float v0[8], v1[8], y0[8], y1[8];
            ldg256_(in + (size_t)base * 8, v0);
            ldg256_(in + (size_t)idx1 * 8, v1);
            quant_f8_(v0, y0);
            stg256_stream_(out + (size_t)base * 8, y0);
            quant_f8_(v1, y1);
            stg256_stream_(out + (size_t)idx1 * 8, y1);
        } else {
            float v0[8], y0[8];
            ldg256_(in + (size_t)base * 8, v0);
            quant_f8_(v0, y0);
            stg256_stream_(out + (size_t)base * 8, y0);
        }
    }
}

extern "C" void kernel_launch(void* const* d_in, const int* in_sizes, int n_in,
                              void* d_out, int out_size) {
    const float* in  = (const float*)d_in[0];
    float*       out = (float*)d_out;
    int n = in_sizes[0];

    if (n % TILE_FLOATS == 0 && n / TILE_FLOATS >= 1) {
        int ntiles = n / TILE_FLOATS;
        int grid = PIPE_GRID < ntiles ? PIPE_GRID : ntiles;
        static bool attr_set = false;
        if (!attr_set) {
            cudaFuncSetAttribute(actquant_nvfp4_pipe,
                                 cudaFuncAttributeMaxDynamicSharedMemorySize,
                                 STAGES * TILE_BYTES);
            attr_set = true;
        }
        actquant_nvfp4_pipe<<<grid, THREADS, STAGES * TILE_BYTES>>>(in, out,
                                                                    ntiles);
    } else {
        int nvec8 = n / 8;
        int threads = 256;
        int blocks  = 1064;
        int maxb = (nvec8 + threads - 1) / threads;
        if (blocks > maxb) blocks = maxb > 0 ? maxb : 1;
        actquant_nvfp4_kernel<<<blocks, threads>>>(in, out, nvec8);
    }
}

// round 16
// speedup vs baseline: 1.2000x; 1.2000x over previous
#include <cuda_runtime.h>
#include <cstdint>

__device__ __forceinline__ float rcp_approx_(float x) {
    float r;
    asm("rcp.approx.f32 %0, %1;" : "=f"(r) : "f"(x));
    return r;
}

// 256-bit global load/store (sm_100+, PTX 8.7), 32B-aligned.
// L2 policy (validated R9 vs R11): INPUT re-read every replay -> evict_last
// keeps it L2-resident (loads are latency-critical). OUTPUT never read ->
// evict_first streams it without displacing the input.
__device__ __forceinline__ void ldg256_(const float* p, float r[8]) {
    asm volatile("ld.global.nc.L2::evict_last.v8.f32 "
                 "{%0,%1,%2,%3,%4,%5,%6,%7}, [%8];"
                 : "=f"(r[0]), "=f"(r[1]), "=f"(r[2]), "=f"(r[3]),
                   "=f"(r[4]), "=f"(r[5]), "=f"(r[6]), "=f"(r[7])
                 : "l"(p));
}
__device__ __forceinline__ void stg256_(float* p, const float r[8]) {
    asm volatile("st.global.L2::evict_first.v8.f32 "
                 "[%0], {%1,%2,%3,%4,%5,%6,%7,%8};"
                 :: "l"(p),
                    "f"(r[0]), "f"(r[1]), "f"(r[2]), "f"(r[3]),
                    "f"(r[4]), "f"(r[5]), "f"(r[6]), "f"(r[7])
                 : "memory");
}

#define GMF_D 0.16666667163372039794921875  /* fp32(1/6) = 0x3E2AAAAB, as double */

// Core: one float8 (half of a 16-elem group). Lane PAIRS own whole groups.
__device__ __forceinline__ void quant_f8_(const float x[8], float y[8]) {
    const float C   = (float)(1.0 / (6.0 * GMF_D));   // RN(1/(6*gm))
    const float GMH = (float)(GMF_D * 0.5);           // gm/2, exact halving

    // Group amax: per-thread partial over 8 + 1 butterfly over the lane pair.
    float a01 = fmaxf(fabsf(x[0]), fabsf(x[1]));
    float a23 = fmaxf(fabsf(x[2]), fabsf(x[3]));
    float a45 = fmaxf(fabsf(x[4]), fabsf(x[5]));
    float a67 = fmaxf(fabsf(x[6]), fabsf(x[7]));
    float ax  = fmaxf(fmaxf(a01, a23), fmaxf(a45, a67));
    ax = fmaxf(ax, __shfl_xor_sync(0xFFFFFFFFu, ax, 1));

    // sraw = (amax/gm)/6 ~= amax * C (<=1 ulp).
    float sraw = ax * C;

    // e4m3 rounding: keep top-3 mantissa bits, round-half-DOWN
    // ((low20 > 0x80000) <=> (low20 + 0x7FFFF) carries), clamp [2^-7, 480].
    unsigned res = (__float_as_uint(sraw) + 0x7FFFFu) & 0xFFF00000u;
    res = max(res, 0x3C000000u);   // 2^-7
    res = min(res, 0x43F00000u);   // 480
    float scale = __uint_as_float(res);

    // Doubled domain: u' = 2 * x/(gm*scale) = x * (12*rcp(scale)).
    // RN commutes with *2, so u' == 2u exactly; thresholds double exactly.
    float R2  = 12.0f * rcp_approx_(scale);
    float sg2 = scale * GMH;   // out = q' * (scale*gm/2), q' = doubled bucket

#pragma unroll
    for (int i = 0; i < 8; i++) {
        float u = x[i] * R2;
        float a = fabsf(u);

        // Bit-round valid only where doubled-E2M1 == 1-mantissa-bit grid:
        // binades [2,4)={2,3}, [4,8)={4,6}, [8,16)={8,12}. Clamp to [2,12].
        float a2 = fminf(fmaxf(a, 2.0f), 12.0f);
        unsigned qb = (__float_as_uint(a2) + 0x00201000u) & 0xFFC00000u;
        float q = __uint_as_float(qb);

        // Linear low buckets {0,1,2}: doubled thresholds (exact binary).
        q = (a >= 1.49951171875f)   ? q : 1.0f;
        q = (a >= 0.4998779296875f) ? q : 0.0f;

        // Sign from u (one LOP3), then single output multiply.
        float qs = __uint_as_float(__float_as_uint(q) |
                                   (__float_as_uint(u) & 0x80000000u));
        y[i] = qs * sg2;
    }
}

// Persistent single-wave grid: 912 blocks = 152 SMs x 6 resident blocks
// (the R9 config with the proven zero replay gap). Hot loop runs a uniform,
// guard-free iteration count (identical for every thread -> perfect SM
// balance at 912 = 6*152); the <=1 ragged iteration is handled once at the
// end. Pointer-marching induction, VPT=2 front-batched LDG.256.
__global__ __launch_bounds__(256, 6)
void actquant_nvfp4_kernel(const float* __restrict__ in,
                           float* __restrict__ out,
                           int nvec8) {
    const int    t  = blockIdx.x * blockDim.x + threadIdx.x;
    const int    S  = gridDim.x * blockDim.x;   // even -> lane pairs lockstep
    const size_t S8 = (size_t)S * 8;

    // Uniform full double-iterations: every thread does exactly nfull.
    const int nfull = nvec8 / (2 * S);

    const float* ip = in  + (size_t)t * 8;
    float*       op = out + (size_t)t * 8;

#pragma unroll 1
    for (int i = 0; i < nfull; i++) {
        float v0[8], v1[8], y0[8], y1[8];
        ldg256_(ip, v0);
        ldg256_(ip + S8, v1);
        quant_f8_(v0, y0);
        stg256_(op, y0);
        quant_f8_(v1, y1);
        stg256_(op + S8, y1);
        ip += 2 * S8;
        op += 2 * S8;
    }

    // Ragged tail: at most 2 more float8s per thread. Whole lane pairs
    // pass/fail each guard together (S and nvec8 even since GROUP=16 =
    // 2 float8s), so shuffles inside always see live partners.
    int base = t + nfull * 2 * S;
    if (base < nvec8) {
        float v0[8], y0[8];
        ldg256_(ip, v0);
        quant_f8_(v0, y0);
        stg256_(op, y0);
        if (base + S < nvec8) {
            float v1[8], y1[8];
            ldg256_(ip + S8, v1);
            quant_f8_(v1, y1);
            stg256_(op + S8, y1);
        }
    }
}

extern "C" void kernel_launch(void* const* d_in, const int* in_sizes, int n_in,
                              void* d_out, int out_size) {
    const float* in  = (const float*)d_in[0];
    float*       out = (float*)d_out;
    int n = in_sizes[0];
    int nvec8 = n / 8;              // one float8 = half group
    int threads = 256;
    int blocks  = 912;              // 152 SMs x 6 blocks -> one resident wave
    // Never launch more threads than work items (tiny-input safety).
    int maxb = (nvec8 + threads - 1) / threads;
    if (blocks > maxb) blocks = maxb > 0 ? maxb : 1;
    actquant_nvfp4_kernel<<<blocks, threads>>>(in, out, nvec8);
}

// round 17
// speedup vs baseline: 1.2020x; 1.0017x over previous
#include <cuda_runtime.h>
#include <cstdint>

__device__ __forceinline__ float rcp_approx_(float x) {
    float r;
    asm("rcp.approx.f32 %0, %1;" : "=f"(r) : "f"(x));
    return r;
}

// 256-bit global load/store (sm_100+, PTX 8.7), 32B-aligned.
// L2 policy (validated R9 vs R11): INPUT re-read every replay -> evict_last
// keeps it L2-resident (loads are latency-critical). OUTPUT never read ->
// evict_first streams it without displacing the input.
__device__ __forceinline__ void ldg256_(const float* p, float r[8]) {
    asm volatile("ld.global.nc.L2::evict_last.v8.f32 "
                 "{%0,%1,%2,%3,%4,%5,%6,%7}, [%8];"
                 : "=f"(r[0]), "=f"(r[1]), "=f"(r[2]), "=f"(r[3]),
                   "=f"(r[4]), "=f"(r[5]), "=f"(r[6]), "=f"(r[7])
                 : "l"(p));
}
__device__ __forceinline__ void stg256_(float* p, const float r[8]) {
    asm volatile("st.global.L2::evict_first.v8.f32 "
                 "[%0], {%1,%2,%3,%4,%5,%6,%7,%8};"
                 :: "l"(p),
                    "f"(r[0]), "f"(r[1]), "f"(r[2]), "f"(r[3]),
                    "f"(r[4]), "f"(r[5]), "f"(r[6]), "f"(r[7])
                 : "memory");
}

#define GMF_D 0.16666667163372039794921875  /* fp32(1/6) = 0x3E2AAAAB, as double */

// Core: one float8 (half of a 16-elem group). Lane PAIRS own whole groups.
__device__ __forceinline__ void quant_f8_(const float x[8], float y[8]) {
    const float C   = (float)(1.0 / (6.0 * GMF_D));   // RN(1/(6*gm))
    const float GMH = (float)(GMF_D * 0.5);           // gm/2, exact halving

    // Group amax: per-thread partial over 8 + 1 butterfly over the lane pair.
    float a01 = fmaxf(fabsf(x[0]), fabsf(x[1]));
    float a23 = fmaxf(fabsf(x[2]), fabsf(x[3]));
    float a45 = fmaxf(fabsf(x[4]), fabsf(x[5]));
    float a67 = fmaxf(fabsf(x[6]), fabsf(x[7]));
    float ax  = fmaxf(fmaxf(a01, a23), fmaxf(a45, a67));
    ax = fmaxf(ax, __shfl_xor_sync(0xFFFFFFFFu, ax, 1));

    // sraw = (amax/gm)/6 ~= amax * C (<=1 ulp).
    float sraw = ax * C;

    // e4m3 rounding: keep top-3 mantissa bits, round-half-DOWN
    // ((low20 > 0x80000) <=> (low20 + 0x7FFFF) carries), clamp [2^-7, 480].
    unsigned res = (__float_as_uint(sraw) + 0x7FFFFu) & 0xFFF00000u;
    res = max(res, 0x3C000000u);   // 2^-7
    res = min(res, 0x43F00000u);   // 480
    float scale = __uint_as_float(res);

    // Doubled domain: u' = 2 * x/(gm*scale) = x * (12*rcp(scale)).
    // RN commutes with *2, so u' == 2u exactly; thresholds double exactly.
    float R2  = 12.0f * rcp_approx_(scale);
    float sg2 = scale * GMH;   // out = q' * (scale*gm/2), q' = doubled bucket

#pragma unroll
    for (int i = 0; i < 8; i++) {
        float u = x[i] * R2;
        float a = fabsf(u);

        // Bit-round valid only where doubled-E2M1 == 1-mantissa-bit grid:
        // binades [2,4)={2,3}, [4,8)={4,6}, [8,16)={8,12}. Clamp to [2,12].
        float a2 = fminf(fmaxf(a, 2.0f), 12.0f);
        unsigned qb = (__float_as_uint(a2) + 0x00201000u) & 0xFFC00000u;
        float q = __uint_as_float(qb);

        // Linear low buckets {0,1,2}: doubled thresholds (exact binary).
        q = (a >= 1.49951171875f)   ? q : 1.0f;
        q = (a >= 0.4998779296875f) ? q : 0.0f;

        // Sign from u (one LOP3), then single output multiply.
        float qs = __uint_as_float(__float_as_uint(q) |
                                   (__float_as_uint(u) & 0x80000000u));
        y[i] = qs * sg2;
    }
}

// Persistent single-wave grid: 760 blocks = 152 SMs x 5 resident blocks
// (reg cap 51 via launch_bounds fits the double buffer without spill).
// Software-pipelined: iteration i+1's loads are issued BEFORE iteration i's
// compute/stores, giving each load a full iteration (~190 issued instrs) to
// complete instead of stalling the warp at the top of the next iteration.
__global__ __launch_bounds__(256, 5)
void actquant_nvfp4_kernel(const float* __restrict__ in,
                           float* __restrict__ out,
                           int nvec8) {
    const int    t  = blockIdx.x * blockDim.x + threadIdx.x;
    const int    S  = gridDim.x * blockDim.x;   // even -> lane pairs lockstep
    const size_t S8 = (size_t)S * 8;

    // Uniform full double-iterations: every thread does exactly nfull.
    const int nfull = nvec8 / (2 * S);

    const float* ip = in  + (size_t)t * 8;
    float*       op = out + (size_t)t * 8;

    if (nfull > 0) {
        float v0[8], v1[8], n0[8], n1[8], y[8];
        // Prologue: fill current buffers.
        ldg256_(ip, v0);
        ldg256_(ip + S8, v1);

#pragma unroll 1
        for (int i = 0; i < nfull; i++) {
            // Prefetch next iteration. On the last iteration, clamp the
            // pointer back to the current tile (branch-free, always valid).
            const float* ipn = (i + 1 < nfull) ? (ip + 2 * S8) : ip;
            ldg256_(ipn, n0);
            ldg256_(ipn + S8, n1);

            // Compute + store current while the prefetch is in flight.
            quant_f8_(v0, y);
            stg256_(op, y);
            quant_f8_(v1, y);
            stg256_(op + S8, y);

#pragma unroll
            for (int j = 0; j < 8; j++) { v0[j] = n0[j]; v1[j] = n1[j]; }
            ip += 2 * S8;
            op += 2 * S8;
        }
    }

    // Ragged tail: at most 2 more float8s per thread. Whole lane pairs
    // pass/fail each guard together (S and nvec8 even since GROUP=16 =
    // 2 float8s), so shuffles inside always see live partners.
    int base = t + nfull * 2 * S;
    if (base < nvec8) {
        float v0[8], y0[8];
        ldg256_(ip, v0);
        quant_f8_(v0, y0);
        stg256_(op, y0);
        if (base + S < nvec8) {
            float v1[8], y1[8];
            ldg256_(ip + S8, v1);
            quant_f8_(v1, y1);
            stg256_(op + S8, y1);
        }
    }
}

extern "C" void kernel_launch(void* const* d_in, const int* in_sizes, int n_in,
                              void* d_out, int out_size) {
    const float* in  = (const float*)d_in[0];
    float*       out = (float*)d_out;
    int n = in_sizes[0];
    int nvec8 = n / 8;              // one float8 = half group
    int threads = 256;
    int blocks  = 760;              // 152 SMs x 5 blocks -> one resident wave
    // Never launch more threads than work items (tiny-input safety).
    int maxb = (nvec8 + threads - 1) / threads;
    if (blocks > maxb) blocks = maxb > 0 ? maxb : 1;
    actquant_nvfp4_kernel<<<blocks, threads>>>(in, out, nvec8);
}